// round 13
// baseline (speedup 1.0000x reference)
#include <cuda_runtime.h>
#include <cuda_fp16.h>
#include <cstdint>
#include <math.h>

#define TOKENS 4096
#define HD 768
#define ID 3072
#define NE 7
#define NA (TOKENS * 2)   // 8192 assignments (top-2)

#define G1X (ID / 128)    // 24  GEMM1 n-tiles
#define G2X (HD / 128)    // 6   GEMM2 n-tiles
#define YT  (NA / 128)    // 64  row tiles
#define G1_BLOCKS (G1X * YT * NE)   // 10752
#define G2_BLOCKS (G2X * YT * NE)   // 2688

// ---------------- device scratch (static, no allocation) ----------------
__device__ int   d_counts[NE];
__device__ int   d_offsets[NE + 1];
__device__ int   d_cursor[NE];
__device__ int   d_ready[NE * YT];
__device__ int   d_tkExpert[NA];
__device__ float d_tkProb[NA];
__device__ int   d_rowToken[NA];
__device__ float d_rowProb[NA];
__device__ __align__(16) __half d_x_h[(size_t)TOKENS * HD];      // 6 MB
__device__ __align__(16) __half d_W1s[(size_t)NE * HD * ID];     // 33 MB  [e][k][n]
__device__ __align__(16) __half d_W2s[(size_t)NE * ID * HD];     // 33 MB  [e][k][n]
__device__ __align__(16) __half d_h1[(size_t)NA * ID];           // 50 MB

// ---------------- helpers ----------------
__device__ __forceinline__ void mma16816(float* c, const uint32_t* a,
                                         uint32_t b0, uint32_t b1) {
    asm volatile(
        "mma.sync.aligned.m16n8k16.row.col.f32.f16.f16.f32 "
        "{%0,%1,%2,%3}, {%4,%5,%6,%7}, {%8,%9}, {%0,%1,%2,%3};"
        : "+f"(c[0]), "+f"(c[1]), "+f"(c[2]), "+f"(c[3])
        : "r"(a[0]), "r"(a[1]), "r"(a[2]), "r"(a[3]), "r"(b0), "r"(b1));
}

__device__ __forceinline__ void ldsm4(uint32_t* r, uint32_t addr) {
    asm volatile("ldmatrix.sync.aligned.m8n8.x4.shared.b16 {%0,%1,%2,%3}, [%4];"
                 : "=r"(r[0]), "=r"(r[1]), "=r"(r[2]), "=r"(r[3]) : "r"(addr));
}
__device__ __forceinline__ void ldsm4t(uint32_t* r, uint32_t addr) {
    asm volatile("ldmatrix.sync.aligned.m8n8.x4.trans.shared.b16 {%0,%1,%2,%3}, [%4];"
                 : "=r"(r[0]), "=r"(r[1]), "=r"(r[2]), "=r"(r[3]) : "r"(addr));
}

__device__ __forceinline__ void cpasync16(uint32_t dst, const void* src) {
    asm volatile("cp.async.cg.shared.global [%0], [%1], 16;"
                 :: "r"(dst), "l"(src) : "memory");
}
__device__ __forceinline__ void cp_commit() {
    asm volatile("cp.async.commit_group;" ::: "memory");
}
__device__ __forceinline__ void cp_wait1() {
    asm volatile("cp.async.wait_group 1;" ::: "memory");
}

__device__ __forceinline__ uint32_t pack_h(__half a, __half b) {
    __half2 t; t.x = a; t.y = b;
    uint32_t r; memcpy(&r, &t, 4); return r;
}

// ---------------- small utility kernels ----------------
__global__ void reset_counters_kernel() {
    int i = threadIdx.x;
    if (i < NE) { d_counts[i] = 0; d_cursor[i] = 0; }
    for (int j = i; j < NE * YT; j += blockDim.x) d_ready[j] = 0;
}

__global__ void zero_out_kernel(float* out, int n) {
    int i = blockIdx.x * blockDim.x + threadIdx.x;
    if (i < n) out[i] = 0.0f;
}

// vectorized fp32 -> fp16 converters (8 elements per thread), merged
__device__ __forceinline__ void conv8(const float* __restrict__ src,
                                      __half* __restrict__ dst, size_t i) {
    float4 v0 = *(const float4*)(src + i);
    float4 v1 = *(const float4*)(src + i + 4);
    uint4 o;
    o.x = pack_h(__float2half(v0.x), __float2half(v0.y));
    o.y = pack_h(__float2half(v0.z), __float2half(v0.w));
    o.z = pack_h(__float2half(v1.x), __float2half(v1.y));
    o.w = pack_h(__float2half(v1.z), __float2half(v1.w));
    *(uint4*)(dst + i) = o;
}

#define NX ((size_t)TOKENS * HD)
#define NW ((size_t)NE * HD * ID)

__global__ void conv_all_kernel(const float* __restrict__ x,
                                const float* __restrict__ W1,
                                const float* __restrict__ W2) {
    size_t i = ((size_t)blockIdx.x * blockDim.x + threadIdx.x) * 8;
    if (i < NX) conv8(x, d_x_h, i);
    else if (i < NX + NW) conv8(W1, d_W1s, i - NX);
    else if (i < NX + 2 * NW) conv8(W2, d_W2s, i - NX - NW);
}

// ---------------- gate: logits, top-2 softmax, assignment build ----------------
__global__ void gate_kernel(const float* __restrict__ x,
                            const float* __restrict__ gW,
                            const float* __restrict__ gb,
                            float* __restrict__ out_gw) {
    int t = blockIdx.x;
    __shared__ float logits[NE];
    int w = threadIdx.x >> 5;
    int lane = threadIdx.x & 31;
    const float* xr = x + (size_t)t * HD;
    if (w < NE) {
        const float* wr = gW + (size_t)w * HD;
        float s = 0.0f;
        for (int h = lane; h < HD; h += 32) s += xr[h] * wr[h];
        #pragma unroll
        for (int o = 16; o; o >>= 1) s += __shfl_down_sync(0xffffffffu, s, o);
        if (lane == 0) logits[w] = s + gb[w];
    }
    __syncthreads();
    if (threadIdx.x == 0) {
        int i0 = 0;
        #pragma unroll
        for (int e = 1; e < NE; e++) if (logits[e] > logits[i0]) i0 = e;
        int i1 = -1;
        #pragma unroll
        for (int e = 0; e < NE; e++) {
            if (e == i0) continue;
            if (i1 < 0 || logits[e] > logits[i1]) i1 = e;
        }
        float v0 = logits[i0], v1 = logits[i1];
        float e1 = expf(v1 - v0);
        float inv = 1.0f / (1.0f + e1);
        float p0 = inv, p1 = e1 * inv;
        float* gw = out_gw + (size_t)t * NE;
        #pragma unroll
        for (int e = 0; e < NE; e++) gw[e] = 0.0f;
        gw[i0] = p0; gw[i1] = p1;
        d_tkExpert[t * 2 + 0] = i0; d_tkProb[t * 2 + 0] = p0;
        d_tkExpert[t * 2 + 1] = i1; d_tkProb[t * 2 + 1] = p1;
        atomicAdd(&d_counts[i0], 1);
        atomicAdd(&d_counts[i1], 1);
    }
}

__global__ void offsets_kernel() {
    int acc = 0;
    for (int e = 0; e < NE; e++) { d_offsets[e] = acc; acc += d_counts[e]; }
    d_offsets[NE] = acc;
}

__global__ void scatter_kernel() {
    int a = blockIdx.x * blockDim.x + threadIdx.x;
    if (a >= NA) return;
    int e = d_tkExpert[a];
    int pos = d_offsets[e] + atomicAdd(&d_cursor[e], 1);
    d_rowToken[pos] = a >> 1;
    d_rowProb[pos]  = d_tkProb[a];
}

// ---------------- HMMA mainloop ----------------
// Tile 128(M) x 128(N), k-tile 64, 256 threads = 8 warps (2 M x 4 N),
// warp tile 64x32.  Plain fp16 operands.  k-range [k0, k0+64*ktiles).
// cp.async 3-stage pipeline, one __syncthreads per k-tile.
// A smem [128][64] fp16: rows 128B = 8 chunks of 16B, phys chunk = c ^ (r&7).
// B smem [64][128] fp16 k-major: rows 256B = 16 chunks, phys = c ^ (k&7).
#define STG_A 0u
#define STG_B 16384u
#define STG_BYTES 32768u
#define NSTAGE 3
#define DSMEM_BYTES (NSTAGE * 32768)   // 96 KB

template<int KDIM>
__device__ __forceinline__ void mainloop(
    const __half* __restrict__ A,     // [rows][KDIM] fp16
    const __half* __restrict__ B,     // [KDIM][NDIM] fp16
    int NDIM, int n0,
    const int* arow,                  // smem: 128 absolute row indices into A
    uint32_t sm,                      // u32 shared addr of dynamic smem
    float acc[4][4][4])
{
    constexpr int KT = KDIM / 64;
    int tid = threadIdx.x;
    int lane = tid & 31, warp = tid >> 5;
    int warpM = (warp >> 2) * 64;    // 2 M-warps
    int warpN = (warp & 3) * 32;     // 4 N-warps
    int g = lane >> 3;               // ldmatrix group 0..3
    int lr = lane & 7;               // row-in-group

    // ---- cp.async assignments: A 4 chunks, B 4 chunks per thread
    int acr = tid >> 1;              // A row 0..127
    int acb = (tid & 1) * 4;         // chunk base 0 or 4
    const __half* aSrc = A + (size_t)arow[acr] * KDIM + acb * 8;
    uint32_t aD[4];
    #pragma unroll
    for (int i = 0; i < 4; i++)
        aD[i] = (uint32_t)(acr * 128 + (((acb + i) ^ (acr & 7)) << 4));

    int bkr = tid >> 2;              // B k-row 0..63
    int bcb = (tid & 3) * 4;         // chunk base 0,4,8,12
    const __half* bSrc = B + (size_t)bkr * NDIM + n0 + bcb * 8;
    uint32_t bD[4];
    #pragma unroll
    for (int i = 0; i < 4; i++)
        bD[i] = (uint32_t)(bkr * 256 + (((bcb + i) ^ (bkr & 7)) << 4));

    auto load_stage = [&](int kt) {
        uint32_t sb = sm + (uint32_t)(kt % NSTAGE) * STG_BYTES;
        size_t ako = (size_t)kt * 64;
        size_t bko = (size_t)kt * 64 * NDIM;
        #pragma unroll
        for (int i = 0; i < 4; i++)
            cpasync16(sb + STG_A + aD[i], aSrc + ako + i * 8);
        #pragma unroll
        for (int i = 0; i < 4; i++)
            cpasync16(sb + STG_B + bD[i], bSrc + bko + i * 8);
    };

    auto compute_stage = [&](int s) {
        uint32_t sb = sm + (uint32_t)s * STG_BYTES;
        #pragma unroll
        for (int kk = 0; kk < 4; kk++) {
            uint32_t a[4][4], bh[2][4];
            #pragma unroll
            for (int mi = 0; mi < 4; mi++) {
                int row = warpM + mi * 16 + (g & 1) * 8 + lr;
                int ch = (kk * 2 + (g >> 1)) ^ (row & 7);
                ldsm4(a[mi], sb + STG_A + (uint32_t)(row * 128 + ch * 16));
            }
            #pragma unroll
            for (int nh = 0; nh < 2; nh++) {
                int k = kk * 16 + (g & 1) * 8 + lr;
                int n = warpN + nh * 16 + (g >> 1) * 8;
                int ch = (n >> 3) ^ (k & 7);
                ldsm4t(bh[nh], sb + STG_B + (uint32_t)(k * 256 + ch * 16));
            }
            #pragma unroll
            for (int mi = 0; mi < 4; mi++) {
                #pragma unroll
                for (int j = 0; j < 4; j++) {
                    int nh = j >> 1, o = (j & 1) * 2;
                    mma16816(acc[mi][j], a[mi], bh[nh][o], bh[nh][o + 1]);
                }
            }
        }
    };

    load_stage(0); cp_commit();
    load_stage(1); cp_commit();

    for (int kt = 0; kt < KT; kt++) {
        cp_wait1();              // stage kt arrived
        __syncthreads();         // ...and stage slot (kt+2)%3 fully consumed
        if (kt + 2 < KT) load_stage(kt + 2);
        cp_commit();
        compute_stage(kt % NSTAGE);
    }
}

// ===================== fused GEMM1 + GEMM2 =====================
// bid < G1_BLOCKS:  GEMM1 tile (h1 = gelu(x @ W1 + b1)); signals d_ready.
// else:             GEMM2 tile (out += p * (h1 @ W2 + b2)); waits on d_ready.
// Blocks dispatch in bid order -> all GEMM1 blocks scheduled before any GEMM2
// block is resident; GEMM1 never waits => deadlock-free.
__global__ void __launch_bounds__(256, 2)
moe_fused(const float* __restrict__ b1,
          const float* __restrict__ b2,
          float* __restrict__ out) {
    extern __shared__ __align__(16) char dyn_raw[];
    uint32_t sm = (uint32_t)__cvta_generic_to_shared(dyn_raw);

    __shared__ int arow[128];
    __shared__ int stok[128];
    __shared__ float sprob[128];

    int bid = blockIdx.x;
    int tid = threadIdx.x;
    int lane = tid & 31, warp = tid >> 5;
    int warpM = (warp >> 2) * 64, warpN = (warp & 3) * 32;
    int qr = lane >> 2, qc = (lane & 3) * 2;

    if (bid < G1_BLOCKS) {
        // ---------------- GEMM1 ----------------
        int xb = bid % G1X;
        int yb = (bid / G1X) % YT;
        int e  = bid / (G1X * YT);
        int cnt = d_counts[e];
        int rowTile = yb * 128;
        if (rowTile >= cnt) return;
        int base = d_offsets[e];
        int n0 = xb * 128;

        if (tid < 128) {
            int r = rowTile + tid;
            arow[tid] = d_rowToken[base + min(r, cnt - 1)];
        }
        __syncthreads();

        float acc[4][4][4] = {};
        mainloop<HD>(d_x_h, d_W1s + (size_t)e * HD * ID,
                     ID, n0, arow, sm, acc);

        const float* bb = b1 + (size_t)e * ID;
        #pragma unroll
        for (int mi = 0; mi < 4; mi++) {
            #pragma unroll
            for (int rr = 0; rr < 2; rr++) {
                int lrow = warpM + mi * 16 + rr * 8 + qr;
                int gr = rowTile + lrow;
                if (gr >= cnt) continue;
                size_t orow = (size_t)(base + gr) * ID + n0;
                #pragma unroll
                for (int j = 0; j < 4; j++) {
                    int n = warpN + j * 8 + qc;
                    float v0 = acc[mi][j][rr * 2]     + bb[n0 + n];
                    float v1 = acc[mi][j][rr * 2 + 1] + bb[n0 + n + 1];
                    float g0 = 0.5f * v0 * (1.0f + erff(v0 * 0.70710678118654752f));
                    float g1 = 0.5f * v1 * (1.0f + erff(v1 * 0.70710678118654752f));
                    *(uint32_t*)(d_h1 + orow + n) =
                        pack_h(__float2half(g0), __float2half(g1));
                }
            }
        }
        // signal: this (e, rowTile) n-panel is done
        __threadfence();
        __syncthreads();
        if (tid == 0) atomicAdd(&d_ready[e * YT + yb], 1);
    } else {
        // ---------------- GEMM2 ----------------
        int b2id = bid - G1_BLOCKS;
        int xb = b2id % G2X;
        int yb = (b2id / G2X) % YT;
        int e  = b2id / (G2X * YT);
        int cnt = d_counts[e];
        int rowTile = yb * 128;
        if (rowTile >= cnt) return;
        int base = d_offsets[e];
        int n0 = xb * 128;

        if (tid < 128) {
            int r = rowTile + tid;
            int rc = base + min(r, cnt - 1);
            arow[tid]  = rc;
            stok[tid]  = d_rowToken[rc];
            sprob[tid] = d_rowProb[rc];
        }
        // wait until all G1X n-panels of this (e, rowTile) are in h1
        if (tid == 0) {
            while (atomicAdd(&d_ready[e * YT + yb], 0) < G1X) __nanosleep(64);
        }
        __syncthreads();

        float acc[4][4][4] = {};
        mainloop<ID>(d_h1, d_W2s + (size_t)e * ID * HD,
                     HD, n0, arow, sm, acc);

        const float* bb = b2 + (size_t)e * HD;
        #pragma unroll
        for (int mi = 0; mi < 4; mi++) {
            #pragma unroll
            for (int rr = 0; rr < 2; rr++) {
                int lrow = warpM + mi * 16 + rr * 8 + qr;
                int gr = rowTile + lrow;
                if (gr >= cnt) continue;
                int tok = stok[lrow];
                float p = sprob[lrow];
                float* od = out + (size_t)tok * HD + n0;
                #pragma unroll
                for (int j = 0; j < 4; j++) {
                    int n = warpN + j * 8 + qc;
                    atomicAdd(&od[n],     p * (acc[mi][j][rr * 2]     + bb[n0 + n]));
                    atomicAdd(&od[n + 1], p * (acc[mi][j][rr * 2 + 1] + bb[n0 + n + 1]));
                }
            }
        }
    }
}

// ---------------- launch ----------------
extern "C" void kernel_launch(void* const* d_in, const int* in_sizes, int n_in,
                              void* d_out, int out_size) {
    const float* x     = (const float*)d_in[0];
    const float* gateW = (const float*)d_in[1];
    const float* gateB = (const float*)d_in[2];
    const float* W1    = (const float*)d_in[3];
    const float* b1    = (const float*)d_in[4];
    const float* W2    = (const float*)d_in[5];
    const float* b2    = (const float*)d_in[6];
    float* out = (float*)d_out;                    // [TOKENS*HD]
    float* out_gw = out + (size_t)TOKENS * HD;     // [TOKENS*NE]

    cudaFuncSetAttribute(moe_fused, cudaFuncAttributeMaxDynamicSharedMemorySize, DSMEM_BYTES);

    reset_counters_kernel<<<1, 512>>>();
    zero_out_kernel<<<(TOKENS * HD + 255) / 256, 256>>>(out, TOKENS * HD);
    gate_kernel<<<TOKENS, 224>>>(x, gateW, gateB, out_gw);
    offsets_kernel<<<1, 1>>>();
    scatter_kernel<<<(NA + 255) / 256, 256>>>();
    {
        size_t total = (NX + 2 * NW) / 8;
        int blocks = (int)((total + 255) / 256);
        conv_all_kernel<<<blocks, 256>>>(x, W1, W2);
    }

    moe_fused<<<G1_BLOCKS + G2_BLOCKS, 256, DSMEM_BYTES>>>(b1, b2, out);
}

// round 14
// speedup vs baseline: 1.0442x; 1.0442x over previous
#include <cuda_runtime.h>
#include <cuda_fp16.h>
#include <cstdint>
#include <math.h>

#define TOKENS 4096
#define HD 768
#define ID 3072
#define NE 7
#define NA (TOKENS * 2)   // 8192 assignments (top-2)

// ---------------- device scratch (static, no allocation) ----------------
__device__ int   d_counts[NE];
__device__ int   d_offsets[NE + 1];
__device__ int   d_cursor[NE];
__device__ int   d_tkExpert[NA];
__device__ float d_tkProb[NA];
__device__ int   d_rowToken[NA];
__device__ float d_rowProb[NA];
__device__ __align__(16) __half d_x_h[(size_t)TOKENS * HD];      // 6 MB
__device__ __align__(16) __half d_W1s[(size_t)NE * HD * ID];     // 33 MB  [e][k][n]
__device__ __align__(16) __half d_W2s[(size_t)NE * ID * HD];     // 33 MB  [e][k][n]
__device__ __align__(16) __half d_h1[(size_t)NA * ID];           // 50 MB

// ---------------- helpers ----------------
__device__ __forceinline__ void mma16816(float* c, const uint32_t* a,
                                         uint32_t b0, uint32_t b1) {
    asm volatile(
        "mma.sync.aligned.m16n8k16.row.col.f32.f16.f16.f32 "
        "{%0,%1,%2,%3}, {%4,%5,%6,%7}, {%8,%9}, {%0,%1,%2,%3};"
        : "+f"(c[0]), "+f"(c[1]), "+f"(c[2]), "+f"(c[3])
        : "r"(a[0]), "r"(a[1]), "r"(a[2]), "r"(a[3]), "r"(b0), "r"(b1));
}

__device__ __forceinline__ void ldsm4(uint32_t* r, uint32_t addr) {
    asm volatile("ldmatrix.sync.aligned.m8n8.x4.shared.b16 {%0,%1,%2,%3}, [%4];"
                 : "=r"(r[0]), "=r"(r[1]), "=r"(r[2]), "=r"(r[3]) : "r"(addr));
}
__device__ __forceinline__ void ldsm4t(uint32_t* r, uint32_t addr) {
    asm volatile("ldmatrix.sync.aligned.m8n8.x4.trans.shared.b16 {%0,%1,%2,%3}, [%4];"
                 : "=r"(r[0]), "=r"(r[1]), "=r"(r[2]), "=r"(r[3]) : "r"(addr));
}

__device__ __forceinline__ void cpasync16(uint32_t dst, const void* src) {
    asm volatile("cp.async.cg.shared.global [%0], [%1], 16;"
                 :: "r"(dst), "l"(src) : "memory");
}
__device__ __forceinline__ void cp_commit() {
    asm volatile("cp.async.commit_group;" ::: "memory");
}
__device__ __forceinline__ void cp_wait1() {
    asm volatile("cp.async.wait_group 1;" ::: "memory");
}

__device__ __forceinline__ uint32_t pack_h(__half a, __half b) {
    __half2 t; t.x = a; t.y = b;
    uint32_t r; memcpy(&r, &t, 4); return r;
}

// ---------------- small utility kernels ----------------
__global__ void reset_counters_kernel() {
    int i = threadIdx.x;
    if (i < NE) { d_counts[i] = 0; d_cursor[i] = 0; }
}

__global__ void zero_out_kernel(float* out, int n) {
    int i = blockIdx.x * blockDim.x + threadIdx.x;
    if (i < n) out[i] = 0.0f;
}

// vectorized fp32 -> fp16 conversion (8 elements per thread), merged sources
__device__ __forceinline__ void conv8(const float* __restrict__ src,
                                      __half* __restrict__ dst, size_t i) {
    float4 v0 = *(const float4*)(src + i);
    float4 v1 = *(const float4*)(src + i + 4);
    uint4 o;
    o.x = pack_h(__float2half(v0.x), __float2half(v0.y));
    o.y = pack_h(__float2half(v0.z), __float2half(v0.w));
    o.z = pack_h(__float2half(v1.x), __float2half(v1.y));
    o.w = pack_h(__float2half(v1.z), __float2half(v1.w));
    *(uint4*)(dst + i) = o;
}

#define NX ((size_t)TOKENS * HD)
#define NW ((size_t)NE * HD * ID)

__global__ void conv_all_kernel(const float* __restrict__ x,
                                const float* __restrict__ W1,
                                const float* __restrict__ W2) {
    size_t i = ((size_t)blockIdx.x * blockDim.x + threadIdx.x) * 8;
    if (i < NX) conv8(x, d_x_h, i);
    else if (i < NX + NW) conv8(W1, d_W1s, i - NX);
    else if (i < NX + 2 * NW) conv8(W2, d_W2s, i - NX - NW);
}

// ---------------- gate: logits, top-2 softmax, assignment build ----------------
__global__ void gate_kernel(const float* __restrict__ x,
                            const float* __restrict__ gW,
                            const float* __restrict__ gb,
                            float* __restrict__ out_gw) {
    int t = blockIdx.x;
    __shared__ float logits[NE];
    int w = threadIdx.x >> 5;
    int lane = threadIdx.x & 31;
    const float* xr = x + (size_t)t * HD;
    if (w < NE) {
        const float* wr = gW + (size_t)w * HD;
        float s = 0.0f;
        for (int h = lane; h < HD; h += 32) s += xr[h] * wr[h];
        #pragma unroll
        for (int o = 16; o; o >>= 1) s += __shfl_down_sync(0xffffffffu, s, o);
        if (lane == 0) logits[w] = s + gb[w];
    }
    __syncthreads();
    if (threadIdx.x == 0) {
        int i0 = 0;
        #pragma unroll
        for (int e = 1; e < NE; e++) if (logits[e] > logits[i0]) i0 = e;
        int i1 = -1;
        #pragma unroll
        for (int e = 0; e < NE; e++) {
            if (e == i0) continue;
            if (i1 < 0 || logits[e] > logits[i1]) i1 = e;
        }
        float v0 = logits[i0], v1 = logits[i1];
        float e1 = expf(v1 - v0);
        float inv = 1.0f / (1.0f + e1);
        float p0 = inv, p1 = e1 * inv;
        float* gw = out_gw + (size_t)t * NE;
        #pragma unroll
        for (int e = 0; e < NE; e++) gw[e] = 0.0f;
        gw[i0] = p0; gw[i1] = p1;
        d_tkExpert[t * 2 + 0] = i0; d_tkProb[t * 2 + 0] = p0;
        d_tkExpert[t * 2 + 1] = i1; d_tkProb[t * 2 + 1] = p1;
        atomicAdd(&d_counts[i0], 1);
        atomicAdd(&d_counts[i1], 1);
    }
}

__global__ void offsets_kernel() {
    int acc = 0;
    for (int e = 0; e < NE; e++) { d_offsets[e] = acc; acc += d_counts[e]; }
    d_offsets[NE] = acc;
}

__global__ void scatter_kernel() {
    int a = blockIdx.x * blockDim.x + threadIdx.x;
    if (a >= NA) return;
    int e = d_tkExpert[a];
    int pos = d_offsets[e] + atomicAdd(&d_cursor[e], 1);
    d_rowToken[pos] = a >> 1;
    d_rowProb[pos]  = d_tkProb[a];
}

// ---------------- HMMA mainloop (templated on M-tile) ----------------
// Tile MT(M) x 128(N), k-tile 64, NTHREADS = 2*MT (MT/64 M-warp-groups x 4
// N-warps, warp tile 64x32).  Plain fp16 operands.
// cp.async 3-stage pipeline, one __syncthreads per k-tile.
// A smem [MT][64] fp16: rows 128B = 8 chunks of 16B, phys chunk = c ^ (r&7).
// B smem [64][128] fp16 k-major: rows 256B = 16 chunks, phys = c ^ (k&7).
#define NSTAGE 3

template<int KDIM, int MT>
__device__ __forceinline__ void mainloop(
    const __half* __restrict__ A,     // [rows][KDIM] fp16
    const __half* __restrict__ B,     // [KDIM][NDIM] fp16
    int NDIM, int n0,
    const int* arow,                  // smem: MT absolute row indices into A
    uint32_t sm,                      // u32 shared addr of dynamic smem
    float acc[4][4][4])
{
    constexpr int KT = KDIM / 64;
    constexpr int NTHREADS = MT * 2;
    constexpr uint32_t STG_B_OFF = (uint32_t)MT * 128u;          // A bytes/stage
    constexpr uint32_t STG_BYTES = STG_B_OFF + 16384u;
    constexpr int NBCH = 1024 / NTHREADS;    // B chunks per thread (16B each)

    int tid = threadIdx.x;
    int lane = tid & 31, warp = tid >> 5;
    int warpM = (warp >> 2) * 64;
    int warpN = (warp & 3) * 32;
    int g = lane >> 3;               // ldmatrix group 0..3
    int lr = lane & 7;               // row-in-group

    // ---- cp.async A: 4 chunks per thread (rows of 8 chunks)
    int acr = tid >> 1;              // A row 0..MT-1
    int acb = (tid & 1) * 4;         // chunk base 0 or 4
    const __half* aSrc = A + (size_t)arow[acr] * KDIM + acb * 8;
    uint32_t aD[4];
    #pragma unroll
    for (int i = 0; i < 4; i++)
        aD[i] = (uint32_t)(acr * 128 + (((acb + i) ^ (acr & 7)) << 4));

    // ---- cp.async B: NBCH linear chunks per thread (64 rows x 16 chunks)
    uint32_t bD[NBCH];
    const __half* bSrcs[NBCH];
    #pragma unroll
    for (int i = 0; i < NBCH; i++) {
        int c = tid * NBCH + i;
        int bkr = c >> 4, bc = c & 15;
        bD[i] = (uint32_t)(bkr * 256 + ((bc ^ (bkr & 7)) << 4));
        bSrcs[i] = B + (size_t)bkr * NDIM + n0 + bc * 8;
    }

    auto load_stage = [&](int kt) {
        uint32_t sb = sm + (uint32_t)(kt % NSTAGE) * STG_BYTES;
        size_t ako = (size_t)kt * 64;
        size_t bko = (size_t)kt * 64 * NDIM;
        #pragma unroll
        for (int i = 0; i < 4; i++)
            cpasync16(sb + aD[i], aSrc + ako + i * 8);
        #pragma unroll
        for (int i = 0; i < NBCH; i++)
            cpasync16(sb + STG_B_OFF + bD[i], bSrcs[i] + bko);
    };

    auto compute_stage = [&](int s) {
        uint32_t sb = sm + (uint32_t)s * STG_BYTES;
        #pragma unroll
        for (int kk = 0; kk < 4; kk++) {
            uint32_t a[4][4], bh[2][4];
            #pragma unroll
            for (int mi = 0; mi < 4; mi++) {
                int row = warpM + mi * 16 + (g & 1) * 8 + lr;
                int ch = (kk * 2 + (g >> 1)) ^ (row & 7);
                ldsm4(a[mi], sb + (uint32_t)(row * 128 + ch * 16));
            }
            #pragma unroll
            for (int nh = 0; nh < 2; nh++) {
                int k = kk * 16 + (g & 1) * 8 + lr;
                int n = warpN + nh * 16 + (g >> 1) * 8;
                int ch = (n >> 3) ^ (k & 7);
                ldsm4t(bh[nh], sb + STG_B_OFF + (uint32_t)(k * 256 + ch * 16));
            }
            #pragma unroll
            for (int mi = 0; mi < 4; mi++) {
                #pragma unroll
                for (int j = 0; j < 4; j++) {
                    int nh = j >> 1, o = (j & 1) * 2;
                    mma16816(acc[mi][j], a[mi], bh[nh][o], bh[nh][o + 1]);
                }
            }
        }
    };

    load_stage(0); cp_commit();
    load_stage(1); cp_commit();

    for (int kt = 0; kt < KT; kt++) {
        cp_wait1();              // stage kt arrived
        __syncthreads();         // ...and stage slot (kt+2)%3 fully consumed
        if (kt + 2 < KT) load_stage(kt + 2);
        cp_commit();
        compute_stage(kt % NSTAGE);
    }
}

#define DSMEM_G1 (NSTAGE * (256 * 128 + 16384))   // 147456 (MT=256)
#define DSMEM_G2 (NSTAGE * (128 * 128 + 16384))   // 98304  (MT=128)

// ===================== GEMM1: h1 = gelu(x @ W1 + b1), 256x128 tile ============
__global__ void __launch_bounds__(512, 1)
gemm1_hmma(const float* __restrict__ b1) {
    int e = blockIdx.z;
    int cnt = d_counts[e];
    int rowTile = blockIdx.y * 256;
    if (rowTile >= cnt) return;
    int base = d_offsets[e];
    int n0 = blockIdx.x * 128;

    extern __shared__ __align__(16) char dyn_raw[];
    uint32_t sm = (uint32_t)__cvta_generic_to_shared(dyn_raw);

    __shared__ int arow[256];
    int tid = threadIdx.x;
    if (tid < 256) {
        int r = rowTile + tid;
        arow[tid] = d_rowToken[base + min(r, cnt - 1)];
    }
    __syncthreads();

    float acc[4][4][4] = {};
    mainloop<HD, 256>(d_x_h, d_W1s + (size_t)e * HD * ID,
                      ID, n0, arow, sm, acc);

    int lane = tid & 31, warp = tid >> 5;
    int warpM = (warp >> 2) * 64, warpN = (warp & 3) * 32;
    int qr = lane >> 2, qc = (lane & 3) * 2;
    const float* bb = b1 + (size_t)e * ID;
    #pragma unroll
    for (int mi = 0; mi < 4; mi++) {
        #pragma unroll
        for (int rr = 0; rr < 2; rr++) {
            int lrow = warpM + mi * 16 + rr * 8 + qr;
            int gr = rowTile + lrow;
            if (gr >= cnt) continue;
            size_t orow = (size_t)(base + gr) * ID + n0;
            #pragma unroll
            for (int j = 0; j < 4; j++) {
                int n = warpN + j * 8 + qc;
                float v0 = acc[mi][j][rr * 2]     + bb[n0 + n];
                float v1 = acc[mi][j][rr * 2 + 1] + bb[n0 + n + 1];
                float g0 = 0.5f * v0 * (1.0f + erff(v0 * 0.70710678118654752f));
                float g1 = 0.5f * v1 * (1.0f + erff(v1 * 0.70710678118654752f));
                *(uint32_t*)(d_h1 + orow + n) =
                    pack_h(__float2half(g0), __float2half(g1));
            }
        }
    }
}

// ===================== GEMM2: out += p * (h1 @ W2 + b2), 128x128 tile =========
__global__ void __launch_bounds__(256, 2)
gemm2_hmma(const float* __restrict__ b2, float* __restrict__ out) {
    int e = blockIdx.z;
    int cnt = d_counts[e];
    int rowTile = blockIdx.y * 128;
    if (rowTile >= cnt) return;
    int base = d_offsets[e];
    int n0 = blockIdx.x * 128;

    extern __shared__ __align__(16) char dyn_raw[];
    uint32_t sm = (uint32_t)__cvta_generic_to_shared(dyn_raw);

    __shared__ int arow[128];
    __shared__ int stok[128];
    __shared__ float sprob[128];
    int tid = threadIdx.x;
    if (tid < 128) {
        int r = rowTile + tid;
        int rc = base + min(r, cnt - 1);
        arow[tid]  = rc;
        stok[tid]  = d_rowToken[rc];
        sprob[tid] = d_rowProb[rc];
    }
    __syncthreads();

    float acc[4][4][4] = {};
    mainloop<ID, 128>(d_h1, d_W2s + (size_t)e * ID * HD,
                      HD, n0, arow, sm, acc);

    int lane = tid & 31, warp = tid >> 5;
    int warpM = (warp >> 2) * 64, warpN = (warp & 3) * 32;
    int qr = lane >> 2, qc = (lane & 3) * 2;
    const float* bb = b2 + (size_t)e * HD;
    #pragma unroll
    for (int mi = 0; mi < 4; mi++) {
        #pragma unroll
        for (int rr = 0; rr < 2; rr++) {
            int lrow = warpM + mi * 16 + rr * 8 + qr;
            int gr = rowTile + lrow;
            if (gr >= cnt) continue;
            int tok = stok[lrow];
            float p = sprob[lrow];
            float* od = out + (size_t)tok * HD + n0;
            #pragma unroll
            for (int j = 0; j < 4; j++) {
                int n = warpN + j * 8 + qc;
                atomicAdd(&od[n],     p * (acc[mi][j][rr * 2]     + bb[n0 + n]));
                atomicAdd(&od[n + 1], p * (acc[mi][j][rr * 2 + 1] + bb[n0 + n + 1]));
            }
        }
    }
}

// ---------------- launch ----------------
extern "C" void kernel_launch(void* const* d_in, const int* in_sizes, int n_in,
                              void* d_out, int out_size) {
    const float* x     = (const float*)d_in[0];
    const float* gateW = (const float*)d_in[1];
    const float* gateB = (const float*)d_in[2];
    const float* W1    = (const float*)d_in[3];
    const float* b1    = (const float*)d_in[4];
    const float* W2    = (const float*)d_in[5];
    const float* b2    = (const float*)d_in[6];
    float* out = (float*)d_out;                    // [TOKENS*HD]
    float* out_gw = out + (size_t)TOKENS * HD;     // [TOKENS*NE]

    cudaFuncSetAttribute(gemm1_hmma, cudaFuncAttributeMaxDynamicSharedMemorySize, DSMEM_G1);
    cudaFuncSetAttribute(gemm2_hmma, cudaFuncAttributeMaxDynamicSharedMemorySize, DSMEM_G2);

    reset_counters_kernel<<<1, 32>>>();
    zero_out_kernel<<<(TOKENS * HD + 255) / 256, 256>>>(out, TOKENS * HD);
    gate_kernel<<<TOKENS, 224>>>(x, gateW, gateB, out_gw);
    offsets_kernel<<<1, 1>>>();
    scatter_kernel<<<(NA + 255) / 256, 256>>>();
    {
        size_t total = (NX + 2 * NW) / 8;
        int blocks = (int)((total + 255) / 256);
        conv_all_kernel<<<blocks, 256>>>(x, W1, W2);
    }

    dim3 g1(ID / 128, NA / 256, NE);       // (24, 32, 7)
    gemm1_hmma<<<g1, 512, DSMEM_G1>>>(b1);

    dim3 g2(HD / 128, NA / 128, NE);       // (6, 64, 7)
    gemm2_hmma<<<g2, 256, DSMEM_G2>>>(b2, out);
}

// round 15
// speedup vs baseline: 1.0889x; 1.0427x over previous
#include <cuda_runtime.h>
#include <cuda_fp16.h>
#include <cstdint>
#include <math.h>

#define TOKENS 4096
#define HD 768
#define ID 3072
#define NE 7
#define NA (TOKENS * 2)   // 8192 assignments (top-2)

// ---------------- device scratch (static, no allocation) ----------------
__device__ int   d_counts[NE];
__device__ int   d_offsets[NE + 1];
__device__ int   d_cursor[NE];
__device__ int   d_tkExpert[NA];
__device__ float d_tkProb[NA];
__device__ int   d_rowToken[NA];
__device__ float d_rowProb[NA];
__device__ __align__(16) __half d_x_h[(size_t)TOKENS * HD];      // 6 MB
__device__ __align__(16) __half d_W1s[(size_t)NE * HD * ID];     // 33 MB  [e][k][n]
__device__ __align__(16) __half d_W2s[(size_t)NE * ID * HD];     // 33 MB  [e][k][n]
__device__ __align__(16) __half d_h1[(size_t)NA * ID];           // 50 MB

// ---------------- helpers ----------------
__device__ __forceinline__ void mma16816(float* c, const uint32_t* a,
                                         uint32_t b0, uint32_t b1) {
    asm volatile(
        "mma.sync.aligned.m16n8k16.row.col.f32.f16.f16.f32 "
        "{%0,%1,%2,%3}, {%4,%5,%6,%7}, {%8,%9}, {%0,%1,%2,%3};"
        : "+f"(c[0]), "+f"(c[1]), "+f"(c[2]), "+f"(c[3])
        : "r"(a[0]), "r"(a[1]), "r"(a[2]), "r"(a[3]), "r"(b0), "r"(b1));
}

__device__ __forceinline__ void ldsm4(uint32_t* r, uint32_t addr) {
    asm volatile("ldmatrix.sync.aligned.m8n8.x4.shared.b16 {%0,%1,%2,%3}, [%4];"
                 : "=r"(r[0]), "=r"(r[1]), "=r"(r[2]), "=r"(r[3]) : "r"(addr));
}
__device__ __forceinline__ void ldsm4t(uint32_t* r, uint32_t addr) {
    asm volatile("ldmatrix.sync.aligned.m8n8.x4.trans.shared.b16 {%0,%1,%2,%3}, [%4];"
                 : "=r"(r[0]), "=r"(r[1]), "=r"(r[2]), "=r"(r[3]) : "r"(addr));
}

__device__ __forceinline__ void cpasync16(uint32_t dst, const void* src) {
    asm volatile("cp.async.cg.shared.global [%0], [%1], 16;"
                 :: "r"(dst), "l"(src) : "memory");
}
__device__ __forceinline__ void cp_commit() {
    asm volatile("cp.async.commit_group;" ::: "memory");
}
__device__ __forceinline__ void cp_wait1() {
    asm volatile("cp.async.wait_group 1;" ::: "memory");
}

__device__ __forceinline__ uint32_t pack_h(__half a, __half b) {
    __half2 t; t.x = a; t.y = b;
    uint32_t r; memcpy(&r, &t, 4); return r;
}

// ---------------- combo prep kernel: conv + zero + reset ----------------
__device__ __forceinline__ void conv8(const float* __restrict__ src,
                                      __half* __restrict__ dst, size_t i) {
    float4 v0 = *(const float4*)(src + i);
    float4 v1 = *(const float4*)(src + i + 4);
    uint4 o;
    o.x = pack_h(__float2half(v0.x), __float2half(v0.y));
    o.y = pack_h(__float2half(v0.z), __float2half(v0.w));
    o.z = pack_h(__float2half(v1.x), __float2half(v1.y));
    o.w = pack_h(__float2half(v1.z), __float2half(v1.w));
    *(uint4*)(dst + i) = o;
}

#define NX ((size_t)TOKENS * HD)
#define NW ((size_t)NE * HD * ID)
#define ZN ((size_t)TOKENS * HD)          // floats to zero in out

__global__ void combo_kernel(const float* __restrict__ x,
                             const float* __restrict__ W1,
                             const float* __restrict__ W2,
                             float* __restrict__ out) {
    size_t t = (size_t)blockIdx.x * blockDim.x + threadIdx.x;
    size_t i = t * 8;
    if (i < NX) conv8(x, d_x_h, i);
    else if (i < NX + NW) conv8(W1, d_W1s, i - NX);
    else if (i < NX + 2 * NW) conv8(W2, d_W2s, i - NX - NW);

    if (t < ZN / 4)
        *(float4*)(out + t * 4) = make_float4(0.f, 0.f, 0.f, 0.f);
    if (t < NE) { d_counts[t] = 0; d_cursor[t] = 0; }
}

// ---------------- gate: logits, top-2 softmax, assignment build ----------------
__global__ void gate_kernel(const float* __restrict__ x,
                            const float* __restrict__ gW,
                            const float* __restrict__ gb,
                            float* __restrict__ out_gw) {
    int t = blockIdx.x;
    __shared__ float logits[NE];
    int w = threadIdx.x >> 5;
    int lane = threadIdx.x & 31;
    const float* xr = x + (size_t)t * HD;
    if (w < NE) {
        const float* wr = gW + (size_t)w * HD;
        float s = 0.0f;
        for (int h = lane; h < HD; h += 32) s += xr[h] * wr[h];
        #pragma unroll
        for (int o = 16; o; o >>= 1) s += __shfl_down_sync(0xffffffffu, s, o);
        if (lane == 0) logits[w] = s + gb[w];
    }
    __syncthreads();
    if (threadIdx.x == 0) {
        int i0 = 0;
        #pragma unroll
        for (int e = 1; e < NE; e++) if (logits[e] > logits[i0]) i0 = e;
        int i1 = -1;
        #pragma unroll
        for (int e = 0; e < NE; e++) {
            if (e == i0) continue;
            if (i1 < 0 || logits[e] > logits[i1]) i1 = e;
        }
        float v0 = logits[i0], v1 = logits[i1];
        float e1 = expf(v1 - v0);
        float inv = 1.0f / (1.0f + e1);
        float p0 = inv, p1 = e1 * inv;
        float* gw = out_gw + (size_t)t * NE;
        #pragma unroll
        for (int e = 0; e < NE; e++) gw[e] = 0.0f;
        gw[i0] = p0; gw[i1] = p1;
        d_tkExpert[t * 2 + 0] = i0; d_tkProb[t * 2 + 0] = p0;
        d_tkExpert[t * 2 + 1] = i1; d_tkProb[t * 2 + 1] = p1;
        atomicAdd(&d_counts[i0], 1);
        atomicAdd(&d_counts[i1], 1);
    }
}

// scatter with locally computed prefix-sum offsets (no separate offsets kernel)
__global__ void scatter_kernel() {
    int a = blockIdx.x * blockDim.x + threadIdx.x;
    if (a >= NA) return;
    int offs[NE];
    int acc = 0;
    #pragma unroll
    for (int e = 0; e < NE; e++) { offs[e] = acc; acc += d_counts[e]; }
    if (a < NE) d_offsets[a] = offs[a];
    if (a == 0) d_offsets[NE] = acc;
    int e = d_tkExpert[a];
    int pos = offs[e] + atomicAdd(&d_cursor[e], 1);
    d_rowToken[pos] = a >> 1;
    d_rowProb[pos]  = d_tkProb[a];
}

// ---------------- HMMA mainloop (R11 configuration) ----------------
// Tile 128(M) x 128(N), k-tile 64, 256 threads = 8 warps (2 M x 4 N),
// warp tile 64x32.  Plain fp16 operands.
// cp.async 3-stage pipeline, one __syncthreads per k-tile.
// A smem [128][64] fp16: rows 128B = 8 chunks of 16B, phys chunk = c ^ (r&7).
// B smem [64][128] fp16 k-major: rows 256B = 16 chunks, phys = c ^ (k&7).
#define STG_A 0u
#define STG_B 16384u
#define STG_BYTES 32768u
#define NSTAGE 3
#define DSMEM_BYTES (NSTAGE * 32768)   // 96 KB

template<int KDIM>
__device__ __forceinline__ void mainloop(
    const __half* __restrict__ A,     // [rows][KDIM] fp16
    const __half* __restrict__ B,     // [KDIM][NDIM] fp16
    int NDIM, int n0,
    const int* arow,                  // smem: 128 absolute row indices into A
    uint32_t sm,                      // u32 shared addr of dynamic smem
    float acc[4][4][4])
{
    constexpr int KT = KDIM / 64;
    int tid = threadIdx.x;
    int lane = tid & 31, warp = tid >> 5;
    int warpM = (warp >> 2) * 64;    // 2 M-warps
    int warpN = (warp & 3) * 32;     // 4 N-warps
    int g = lane >> 3;               // ldmatrix group 0..3
    int lr = lane & 7;               // row-in-group

    // ---- cp.async assignments: A 4 chunks, B 4 chunks per thread
    int acr = tid >> 1;              // A row 0..127
    int acb = (tid & 1) * 4;         // chunk base 0 or 4
    const __half* aSrc = A + (size_t)arow[acr] * KDIM + acb * 8;
    uint32_t aD[4];
    #pragma unroll
    for (int i = 0; i < 4; i++)
        aD[i] = (uint32_t)(acr * 128 + (((acb + i) ^ (acr & 7)) << 4));

    int bkr = tid >> 2;              // B k-row 0..63
    int bcb = (tid & 3) * 4;         // chunk base 0,4,8,12
    const __half* bSrc = B + (size_t)bkr * NDIM + n0 + bcb * 8;
    uint32_t bD[4];
    #pragma unroll
    for (int i = 0; i < 4; i++)
        bD[i] = (uint32_t)(bkr * 256 + (((bcb + i) ^ (bkr & 7)) << 4));

    auto load_stage = [&](int kt) {
        uint32_t sb = sm + (uint32_t)(kt % NSTAGE) * STG_BYTES;
        size_t ako = (size_t)kt * 64;
        size_t bko = (size_t)kt * 64 * NDIM;
        #pragma unroll
        for (int i = 0; i < 4; i++)
            cpasync16(sb + STG_A + aD[i], aSrc + ako + i * 8);
        #pragma unroll
        for (int i = 0; i < 4; i++)
            cpasync16(sb + STG_B + bD[i], bSrc + bko + i * 8);
    };

    auto compute_stage = [&](int s) {
        uint32_t sb = sm + (uint32_t)s * STG_BYTES;
        #pragma unroll
        for (int kk = 0; kk < 4; kk++) {
            uint32_t a[4][4], bh[2][4];
            #pragma unroll
            for (int mi = 0; mi < 4; mi++) {
                int row = warpM + mi * 16 + (g & 1) * 8 + lr;
                int ch = (kk * 2 + (g >> 1)) ^ (row & 7);
                ldsm4(a[mi], sb + STG_A + (uint32_t)(row * 128 + ch * 16));
            }
            #pragma unroll
            for (int nh = 0; nh < 2; nh++) {
                int k = kk * 16 + (g & 1) * 8 + lr;
                int n = warpN + nh * 16 + (g >> 1) * 8;
                int ch = (n >> 3) ^ (k & 7);
                ldsm4t(bh[nh], sb + STG_B + (uint32_t)(k * 256 + ch * 16));
            }
            #pragma unroll
            for (int mi = 0; mi < 4; mi++) {
                #pragma unroll
                for (int j = 0; j < 4; j++) {
                    int nh = j >> 1, o = (j & 1) * 2;
                    mma16816(acc[mi][j], a[mi], bh[nh][o], bh[nh][o + 1]);
                }
            }
        }
    };

    load_stage(0); cp_commit();
    load_stage(1); cp_commit();

    for (int kt = 0; kt < KT; kt++) {
        cp_wait1();              // stage kt arrived
        __syncthreads();         // ...and stage slot (kt+2)%3 fully consumed
        if (kt + 2 < KT) load_stage(kt + 2);
        cp_commit();
        compute_stage(kt % NSTAGE);
    }
}

// ===================== GEMM1: h1 = gelu(x @ W1 + b1) ==========================
__global__ void __launch_bounds__(256, 2)
gemm1_hmma(const float* __restrict__ b1) {
    int e = blockIdx.z;
    int cnt = d_counts[e];
    int rowTile = blockIdx.y * 128;
    if (rowTile >= cnt) return;
    int base = d_offsets[e];
    int n0 = blockIdx.x * 128;

    extern __shared__ __align__(16) char dyn_raw[];
    uint32_t sm = (uint32_t)__cvta_generic_to_shared(dyn_raw);

    __shared__ int arow[128];
    int tid = threadIdx.x;
    if (tid < 128) {
        int r = rowTile + tid;
        arow[tid] = d_rowToken[base + min(r, cnt - 1)];
    }
    __syncthreads();

    float acc[4][4][4] = {};
    mainloop<HD>(d_x_h, d_W1s + (size_t)e * HD * ID,
                 ID, n0, arow, sm, acc);

    int lane = tid & 31, warp = tid >> 5;
    int warpM = (warp >> 2) * 64, warpN = (warp & 3) * 32;
    int qr = lane >> 2, qc = (lane & 3) * 2;
    const float* bb = b1 + (size_t)e * ID;
    #pragma unroll
    for (int mi = 0; mi < 4; mi++) {
        #pragma unroll
        for (int rr = 0; rr < 2; rr++) {
            int lrow = warpM + mi * 16 + rr * 8 + qr;
            int gr = rowTile + lrow;
            if (gr >= cnt) continue;
            size_t orow = (size_t)(base + gr) * ID + n0;
            #pragma unroll
            for (int j = 0; j < 4; j++) {
                int n = warpN + j * 8 + qc;
                float v0 = acc[mi][j][rr * 2]     + bb[n0 + n];
                float v1 = acc[mi][j][rr * 2 + 1] + bb[n0 + n + 1];
                float g0 = 0.5f * v0 * (1.0f + erff(v0 * 0.70710678118654752f));
                float g1 = 0.5f * v1 * (1.0f + erff(v1 * 0.70710678118654752f));
                *(uint32_t*)(d_h1 + orow + n) =
                    pack_h(__float2half(g0), __float2half(g1));
            }
        }
    }
}

// ===================== GEMM2: out += p * (h1 @ W2 + b2) =======================
__global__ void __launch_bounds__(256, 2)
gemm2_hmma(const float* __restrict__ b2, float* __restrict__ out) {
    int e = blockIdx.z;
    int cnt = d_counts[e];
    int rowTile = blockIdx.y * 128;
    if (rowTile >= cnt) return;
    int base = d_offsets[e];
    int n0 = blockIdx.x * 128;

    extern __shared__ __align__(16) char dyn_raw[];
    uint32_t sm = (uint32_t)__cvta_generic_to_shared(dyn_raw);

    __shared__ int arow[128];
    __shared__ int stok[128];
    __shared__ float sprob[128];
    int tid = threadIdx.x;
    if (tid < 128) {
        int r = rowTile + tid;
        int rc = base + min(r, cnt - 1);
        arow[tid]  = rc;
        stok[tid]  = d_rowToken[rc];
        sprob[tid] = d_rowProb[rc];
    }
    __syncthreads();

    float acc[4][4][4] = {};
    mainloop<ID>(d_h1, d_W2s + (size_t)e * ID * HD,
                 HD, n0, arow, sm, acc);

    int lane = tid & 31, warp = tid >> 5;
    int warpM = (warp >> 2) * 64, warpN = (warp & 3) * 32;
    int qr = lane >> 2, qc = (lane & 3) * 2;
    const float* bb = b2 + (size_t)e * HD;
    #pragma unroll
    for (int mi = 0; mi < 4; mi++) {
        #pragma unroll
        for (int rr = 0; rr < 2; rr++) {
            int lrow = warpM + mi * 16 + rr * 8 + qr;
            int gr = rowTile + lrow;
            if (gr >= cnt) continue;
            int tok = stok[lrow];
            float p = sprob[lrow];
            float* od = out + (size_t)tok * HD + n0;
            #pragma unroll
            for (int j = 0; j < 4; j++) {
                int n = warpN + j * 8 + qc;
                atomicAdd(&od[n],     p * (acc[mi][j][rr * 2]     + bb[n0 + n]));
                atomicAdd(&od[n + 1], p * (acc[mi][j][rr * 2 + 1] + bb[n0 + n + 1]));
            }
        }
    }
}

// ---------------- launch ----------------
extern "C" void kernel_launch(void* const* d_in, const int* in_sizes, int n_in,
                              void* d_out, int out_size) {
    const float* x     = (const float*)d_in[0];
    const float* gateW = (const float*)d_in[1];
    const float* gateB = (const float*)d_in[2];
    const float* W1    = (const float*)d_in[3];
    const float* b1    = (const float*)d_in[4];
    const float* W2    = (const float*)d_in[5];
    const float* b2    = (const float*)d_in[6];
    float* out = (float*)d_out;                    // [TOKENS*HD]
    float* out_gw = out + (size_t)TOKENS * HD;     // [TOKENS*NE]

    cudaFuncSetAttribute(gemm1_hmma, cudaFuncAttributeMaxDynamicSharedMemorySize, DSMEM_BYTES);
    cudaFuncSetAttribute(gemm2_hmma, cudaFuncAttributeMaxDynamicSharedMemorySize, DSMEM_BYTES);

    {   // conv(x, W1, W2) + zero(out) + reset counters, one launch
        size_t total = (NX + 2 * NW) / 8;
        int blocks = (int)((total + 255) / 256);
        combo_kernel<<<blocks, 256>>>(x, W1, W2, out);
    }
    gate_kernel<<<TOKENS, 224>>>(x, gateW, gateB, out_gw);
    scatter_kernel<<<(NA + 255) / 256, 256>>>();

    dim3 g1(ID / 128, NA / 128, NE);       // (24, 64, 7)
    gemm1_hmma<<<g1, 256, DSMEM_BYTES>>>(b1);

    dim3 g2(HD / 128, NA / 128, NE);       // (6, 64, 7)
    gemm2_hmma<<<g2, 256, DSMEM_BYTES>>>(b2, out);
}